// round 1
// baseline (speedup 1.0000x reference)
#include <cuda_runtime.h>
#include <math.h>

#define NPTS 16384
#define KMAX 64
#define R2   (1.0f / 256.0f)
#define TILE 2048

// ---- scratch (static __device__ arrays; no allocation allowed) ----
__device__ int   g_cloud_start[16];
__device__ int   g_nbr_idx[NPTS * KMAX];
__device__ int   g_nbr_cnt[NPTS];
__device__ float g_feat_a[NPTS * 8];
__device__ float g_feat_b[NPTS * 16];

// ---------------------------------------------------------------------------
// Kernel 0: cloud ranges from sorted batch vector. g_cloud_start[c] = first
// index of cloud c; g_cloud_start[8] = NPTS. Empty clouds collapse to the
// next cloud's start.
// ---------------------------------------------------------------------------
__global__ void cloud_bounds_kernel(const int* __restrict__ batch) {
    __shared__ int s[9];
    if (threadIdx.x < 9) s[threadIdx.x] = NPTS;
    __syncthreads();
    for (int i = threadIdx.x; i < NPTS; i += blockDim.x) {
        int b = batch[i];
        if (i == 0 || batch[i - 1] != b) atomicMin(&s[b], i);
    }
    __syncthreads();
    if (threadIdx.x == 0) {
        s[8] = NPTS;
        for (int c = 7; c >= 0; --c)
            if (s[c] == NPTS) s[c] = s[c + 1];
        for (int c = 0; c <= 8; ++c) g_cloud_start[c] = s[c];
    }
}

// ---------------------------------------------------------------------------
// Kernel 1: radius graph. One thread per point; block tiles its cloud's
// positions into smem. Expected ~2 neighbors/point; KMAX=64 never truncates
// in practice (and max-agg is order invariant, so order doesn't matter).
// Also writes the pos copy and batch copy into the output tuple layout:
//   out[0 : 3N)        = pos
//   out[3N : 35N)      = features (written by conv_c)
//   out[35N : 36N)     = batch (as float)
// ---------------------------------------------------------------------------
__global__ __launch_bounds__(128) void radius_kernel(
    const float* __restrict__ pos, const int* __restrict__ batch,
    float* __restrict__ out)
{
    __shared__ float4 sp[TILE];   // x,y,z,|p|^2
    __shared__ int    sb[TILE];

    const int i  = blockIdx.x * 128 + threadIdx.x;
    const float px = pos[3 * i + 0];
    const float py = pos[3 * i + 1];
    const float pz = pos[3 * i + 2];
    const float si = px * px + py * py + pz * pz;
    const int myb = batch[i];

    // output copies (pos + batch sections of the tuple)
    out[3 * i + 0] = px;
    out[3 * i + 1] = py;
    out[3 * i + 2] = pz;
    out[(size_t)NPTS * 35 + i] = (float)myb;

    // candidate range: union of clouds present in this block (<= 2 clouds)
    const int base   = blockIdx.x * 128;
    const int jstart = g_cloud_start[batch[base]];
    const int jend   = g_cloud_start[batch[base + 127] + 1];

    int  cnt   = 0;
    int* myidx = g_nbr_idx + (size_t)i * KMAX;

    for (int t = jstart; t < jend; t += TILE) {
        const int m = min(TILE, jend - t);
        for (int k = threadIdx.x; k < m; k += 128) {
            const int j = t + k;
            const float x = pos[3 * j + 0];
            const float y = pos[3 * j + 1];
            const float z = pos[3 * j + 2];
            sp[k] = make_float4(x, y, z, x * x + y * y + z * z);
            sb[k] = batch[j];
        }
        __syncthreads();
        for (int k = 0; k < m; ++k) {
            const float4 q  = sp[k];
            const float dot = px * q.x + py * q.y + pz * q.z;
            // same formula as reference: s_i + s_j - 2*dot (clamp irrelevant for <= R2)
            const float d2  = si + q.w - 2.0f * dot;
            if (d2 <= R2 && sb[k] == myb) {
                if (cnt < KMAX) myidx[cnt++] = t + k;
            }
        }
        __syncthreads();
    }
    g_nbr_cnt[i] = cnt;
}

// ---------------------------------------------------------------------------
// Fused PointNetConv + CELU.
//   msg_j = relu([x_j, pos_j - pos_i] @ W1 + b1)
//   agg   = max_j msg_j          (cnt >= 1 always: self-loop)
//   out_i = celu(agg @ W2 + b2)
// Weights live in smem (broadcast loads, conflict-free).
// ---------------------------------------------------------------------------
__device__ __forceinline__ float celu1(float v) {
    return v > 0.0f ? v : expm1f(v);
}

template <int CIN, int CMID, int COUT>
__global__ __launch_bounds__(128) void conv_kernel(
    const float* __restrict__ x, const float* __restrict__ pos,
    const float* __restrict__ W1, const float* __restrict__ b1,
    const float* __restrict__ W2, const float* __restrict__ b2,
    float* __restrict__ out)
{
    __shared__ float sW1[(CIN + 3) * CMID];
    __shared__ float sB1[CMID];
    __shared__ float sW2[CMID * COUT];
    __shared__ float sB2[COUT];

    for (int k = threadIdx.x; k < (CIN + 3) * CMID; k += blockDim.x) sW1[k] = W1[k];
    for (int k = threadIdx.x; k < CMID;             k += blockDim.x) sB1[k] = b1[k];
    for (int k = threadIdx.x; k < CMID * COUT;      k += blockDim.x) sW2[k] = W2[k];
    for (int k = threadIdx.x; k < COUT;             k += blockDim.x) sB2[k] = b2[k];
    __syncthreads();

    const int i  = blockIdx.x * 128 + threadIdx.x;
    const float px = pos[3 * i + 0];
    const float py = pos[3 * i + 1];
    const float pz = pos[3 * i + 2];

    float acc[CMID];
#pragma unroll
    for (int m = 0; m < CMID; ++m) acc[m] = -INFINITY;

    const int  cnt   = g_nbr_cnt[i];
    const int* myidx = g_nbr_idx + (size_t)i * KMAX;

    for (int n = 0; n < cnt; ++n) {
        const int j = myidx[n];
        float xj[CIN];
#pragma unroll
        for (int d = 0; d < CIN; ++d) xj[d] = x[(size_t)j * CIN + d];
        const float rx = pos[3 * j + 0] - px;
        const float ry = pos[3 * j + 1] - py;
        const float rz = pos[3 * j + 2] - pz;
#pragma unroll
        for (int m = 0; m < CMID; ++m) {
            float h = sB1[m];
#pragma unroll
            for (int d = 0; d < CIN; ++d) h = fmaf(xj[d], sW1[d * CMID + m], h);
            h = fmaf(rx, sW1[(CIN + 0) * CMID + m], h);
            h = fmaf(ry, sW1[(CIN + 1) * CMID + m], h);
            h = fmaf(rz, sW1[(CIN + 2) * CMID + m], h);
            h = fmaxf(h, 0.0f);         // relu BEFORE max-agg (as reference)
            acc[m] = fmaxf(acc[m], h);
        }
    }

#pragma unroll
    for (int o = 0; o < COUT; ++o) {
        float v = sB2[o];
#pragma unroll
        for (int m = 0; m < CMID; ++m) v = fmaf(acc[m], sW2[m * COUT + o], v);
        out[(size_t)i * COUT + o] = celu1(v);
    }
}

// ---------------------------------------------------------------------------
// Launch. Inputs (metadata order):
//  0 pos [N,3] f32 | 1 rgb (unused) | 2 batch [N] int
//  3 W1a[6,8] 4 b1a[8] 5 W2a[8,8] 6 b2a[8]
//  7 W1b[11,16] 8 b1b[16] 9 W2b[16,16] 10 b2b[16]
// 11 W1c[19,32] 12 b1c[32] 13 W2c[32,32] 14 b2c[32]
// Output: concat [pos(3N) | feat(32N) | batch(N)] as float32.
// ---------------------------------------------------------------------------
extern "C" void kernel_launch(void* const* d_in, const int* in_sizes, int n_in,
                              void* d_out, int out_size)
{
    const float* pos   = (const float*)d_in[0];
    const int*   batch = (const int*)d_in[2];
    const float* W1a = (const float*)d_in[3];
    const float* b1a = (const float*)d_in[4];
    const float* W2a = (const float*)d_in[5];
    const float* b2a = (const float*)d_in[6];
    const float* W1b = (const float*)d_in[7];
    const float* b1b = (const float*)d_in[8];
    const float* W2b = (const float*)d_in[9];
    const float* b2b = (const float*)d_in[10];
    const float* W1c = (const float*)d_in[11];
    const float* b1c = (const float*)d_in[12];
    const float* W2c = (const float*)d_in[13];
    const float* b2c = (const float*)d_in[14];

    float* out = (float*)d_out;

    void *pfa = nullptr, *pfb = nullptr;
    cudaGetSymbolAddress(&pfa, g_feat_a);
    cudaGetSymbolAddress(&pfb, g_feat_b);

    cloud_bounds_kernel<<<1, 256>>>(batch);
    radius_kernel<<<NPTS / 128, 128>>>(pos, batch, out);
    conv_kernel<3, 8, 8><<<NPTS / 128, 128>>>(pos, pos, W1a, b1a, W2a, b2a,
                                              (float*)pfa);
    conv_kernel<8, 16, 16><<<NPTS / 128, 128>>>((const float*)pfa, pos,
                                                W1b, b1b, W2b, b2b, (float*)pfb);
    conv_kernel<16, 32, 32><<<NPTS / 128, 128>>>((const float*)pfb, pos,
                                                 W1c, b1c, W2c, b2c,
                                                 out + (size_t)NPTS * 3);
}

// round 2
// speedup vs baseline: 1.7971x; 1.7971x over previous
#include <cuda_runtime.h>
#include <math.h>

#define NPTS  16384
#define KMAX  64
#define R2    (1.0f / 256.0f)
#define NCELL 32768   // 8 clouds * 16^3 cells, cell edge = r = 1/16

// ---- scratch (static __device__ arrays; no allocation allowed) ----
__device__ int    g_cell_count[NCELL];
__device__ int    g_cell_start[NCELL + 1];
__device__ int    g_cell_fill[NCELL];
__device__ int    g_cell_of[NPTS];
__device__ float4 g_sorted[NPTS];       // x,y,z,|p|^2 in cell-sorted order
__device__ int    g_sorted_idx[NPTS];   // original index
__device__ int    g_nbr_idx[NPTS * KMAX];
__device__ int    g_nbr_cnt[NPTS];
__device__ float  g_h0a[NPTS * 8];      // x@W1x + b1 per layer
__device__ float  g_h0b[NPTS * 16];
__device__ float  g_h0c[NPTS * 32];

// ---------------------------------------------------------------------------
// K1: cell assignment + histogram. Also writes pos/batch copies into the
// output tuple: out = [pos(3N) | feat(32N) | batch(N)].
// ---------------------------------------------------------------------------
__global__ __launch_bounds__(128) void count_kernel(
    const float* __restrict__ pos, const int* __restrict__ batch,
    float* __restrict__ out)
{
    const int i = blockIdx.x * 128 + threadIdx.x;
    const float px = pos[3 * i + 0];
    const float py = pos[3 * i + 1];
    const float pz = pos[3 * i + 2];
    const int b = batch[i];

    out[3 * i + 0] = px;
    out[3 * i + 1] = py;
    out[3 * i + 2] = pz;
    out[(size_t)NPTS * 35 + i] = (float)b;

    int cx = min(15, max(0, (int)(px * 16.0f)));
    int cy = min(15, max(0, (int)(py * 16.0f)));
    int cz = min(15, max(0, (int)(pz * 16.0f)));
    int c = (b << 12) | (cz << 8) | (cy << 4) | cx;
    g_cell_of[i] = c;
    atomicAdd(&g_cell_count[c], 1);
}

// ---------------------------------------------------------------------------
// K2: exclusive prefix sum over 32768 cells (one block of 1024 threads,
// 32 cells/thread + Hillis–Steele scan of partials).
// ---------------------------------------------------------------------------
__global__ __launch_bounds__(1024) void scan_kernel()
{
    __shared__ int sp[1024];
    const int t = threadIdx.x;
    const int base = t * 32;
    int local[32];
    int sum = 0;
#pragma unroll
    for (int k = 0; k < 32; ++k) { local[k] = g_cell_count[base + k]; sum += local[k]; }
    sp[t] = sum;
    __syncthreads();
    for (int off = 1; off < 1024; off <<= 1) {
        int v = (t >= off) ? sp[t - off] : 0;
        __syncthreads();
        sp[t] += v;
        __syncthreads();
    }
    int run = sp[t] - sum;  // exclusive prefix of this chunk
#pragma unroll
    for (int k = 0; k < 32; ++k) {
        g_cell_start[base + k] = run;
        g_cell_fill[base + k]  = run;
        run += local[k];
    }
    if (t == 1023) g_cell_start[NCELL] = run;
}

// ---------------------------------------------------------------------------
// K3: scatter points into cell-sorted order (with precomputed |p|^2).
// ---------------------------------------------------------------------------
__global__ __launch_bounds__(128) void scatter_kernel(const float* __restrict__ pos)
{
    const int i = blockIdx.x * 128 + threadIdx.x;
    const float px = pos[3 * i + 0];
    const float py = pos[3 * i + 1];
    const float pz = pos[3 * i + 2];
    const int c = g_cell_of[i];
    const int p = atomicAdd(&g_cell_fill[c], 1);
    g_sorted[p] = make_float4(px, py, pz, px * px + py * py + pz * pz);
    g_sorted_idx[p] = i;
}

// ---------------------------------------------------------------------------
// K4: radius query via 27-cell stencil = 9 contiguous sorted runs.
// Cell id encodes the cloud, so same-cloud filtering is implicit.
// Self-loop (d2=0) always included -> cnt >= 1.
// ---------------------------------------------------------------------------
__global__ __launch_bounds__(128) void query_kernel(const float* __restrict__ pos)
{
    const int i = blockIdx.x * 128 + threadIdx.x;
    const float px = pos[3 * i + 0];
    const float py = pos[3 * i + 1];
    const float pz = pos[3 * i + 2];
    const float si = px * px + py * py + pz * pz;

    const int c  = g_cell_of[i];
    const int cx = c & 15, cy = (c >> 4) & 15, cz = (c >> 8) & 15;
    const int cloudbase = c & 0xF000;
    const int x0 = max(cx - 1, 0), x1 = min(cx + 1, 15);

    int  cnt   = 0;
    int* myidx = g_nbr_idx + (size_t)i * KMAX;

#pragma unroll
    for (int dz = -1; dz <= 1; ++dz) {
        const int z = cz + dz;
        if ((unsigned)z > 15u) continue;
#pragma unroll
        for (int dy = -1; dy <= 1; ++dy) {
            const int y = cy + dy;
            if ((unsigned)y > 15u) continue;
            const int rb = cloudbase | (z << 8) | (y << 4);
            const int js = g_cell_start[rb + x0];
            const int je = g_cell_start[rb + x1 + 1];
            for (int j = js; j < je; ++j) {
                const float4 q = g_sorted[j];
                const float dot = px * q.x + py * q.y + pz * q.z;
                const float d2 = si + q.w - 2.0f * dot;   // reference's formula
                if (d2 <= R2 && cnt < KMAX) myidx[cnt++] = g_sorted_idx[j];
            }
        }
    }
    g_nbr_cnt[i] = cnt;
}

// ---------------------------------------------------------------------------
// K5: layer-a precompute  h0a[i] = pos[i] @ W1a[0:3] + b1a   (rows 0..2)
// ---------------------------------------------------------------------------
__global__ __launch_bounds__(128) void pre_a_kernel(
    const float* __restrict__ pos,
    const float* __restrict__ W1, const float* __restrict__ b1)
{
    const int i = blockIdx.x * 128 + threadIdx.x;
    const float px = pos[3 * i + 0];
    const float py = pos[3 * i + 1];
    const float pz = pos[3 * i + 2];
#pragma unroll
    for (int m = 0; m < 8; ++m) {
        float h = b1[m];
        h = fmaf(px, W1[0 * 8 + m], h);
        h = fmaf(py, W1[1 * 8 + m], h);
        h = fmaf(pz, W1[2 * 8 + m], h);
        g_h0a[(size_t)i * 8 + m] = h;
    }
}

__device__ __forceinline__ float celu1(float v) {
    return v > 0.0f ? v : expm1f(v);
}

// ---------------------------------------------------------------------------
// Fused pair stage:
//   acc[m] = max_j relu( h0[j][m] + rel . W1rel[:,m] )
//   v[o]   = celu( acc @ W2 + b2 )
//   CNEXT>0:  write h0next[i][m] = b1n[m] + v @ W1n[0:COUT]   (next layer's x-part)
//   CNEXT==0: write v to out (final features)
// W1rel = rows [CIN .. CIN+3) of the layer's W1 (rel part).
// ---------------------------------------------------------------------------
template <int CMID, int COUT, int CNEXT>
__global__ __launch_bounds__(128) void pair_kernel(
    const float* __restrict__ h0, const float* __restrict__ pos,
    const float* __restrict__ W1rel,                       // [3, CMID]
    const float* __restrict__ W2, const float* __restrict__ b2,   // [CMID,COUT],[COUT]
    const float* __restrict__ W1n, const float* __restrict__ b1n, // [>=COUT,CNEXT],[CNEXT]
    float* __restrict__ outbuf)
{
    __shared__ float sW1r[3 * CMID];
    __shared__ float sW2[CMID * COUT];
    __shared__ float sB2[COUT];
    __shared__ float sW1n[(CNEXT > 0 ? COUT * CNEXT : 1)];
    __shared__ float sB1n[(CNEXT > 0 ? CNEXT : 1)];

    for (int k = threadIdx.x; k < 3 * CMID;    k += blockDim.x) sW1r[k] = W1rel[k];
    for (int k = threadIdx.x; k < CMID * COUT; k += blockDim.x) sW2[k]  = W2[k];
    for (int k = threadIdx.x; k < COUT;        k += blockDim.x) sB2[k]  = b2[k];
    if (CNEXT > 0) {
        for (int k = threadIdx.x; k < COUT * CNEXT; k += blockDim.x) sW1n[k] = W1n[k];
        for (int k = threadIdx.x; k < CNEXT;        k += blockDim.x) sB1n[k] = b1n[k];
    }
    __syncthreads();

    const int i = blockIdx.x * 128 + threadIdx.x;
    const float px = pos[3 * i + 0];
    const float py = pos[3 * i + 1];
    const float pz = pos[3 * i + 2];

    float acc[CMID];
#pragma unroll
    for (int m = 0; m < CMID; ++m) acc[m] = -INFINITY;

    const int  cnt   = g_nbr_cnt[i];
    const int* myidx = g_nbr_idx + (size_t)i * KMAX;

    for (int n = 0; n < cnt; ++n) {
        const int j = myidx[n];
        const float rx = pos[3 * j + 0] - px;
        const float ry = pos[3 * j + 1] - py;
        const float rz = pos[3 * j + 2] - pz;
        float h0j[CMID];
        const float4* h4 = reinterpret_cast<const float4*>(h0) + (size_t)j * (CMID / 4);
#pragma unroll
        for (int q = 0; q < CMID / 4; ++q) {
            const float4 v = h4[q];
            h0j[4 * q + 0] = v.x; h0j[4 * q + 1] = v.y;
            h0j[4 * q + 2] = v.z; h0j[4 * q + 3] = v.w;
        }
#pragma unroll
        for (int m = 0; m < CMID; ++m) {
            float h = h0j[m];
            h = fmaf(rx, sW1r[0 * CMID + m], h);
            h = fmaf(ry, sW1r[1 * CMID + m], h);
            h = fmaf(rz, sW1r[2 * CMID + m], h);
            h = fmaxf(h, 0.0f);
            acc[m] = fmaxf(acc[m], h);
        }
    }

    float v[COUT];
#pragma unroll
    for (int o = 0; o < COUT; ++o) {
        float s = sB2[o];
#pragma unroll
        for (int m = 0; m < CMID; ++m) s = fmaf(acc[m], sW2[m * COUT + o], s);
        v[o] = celu1(s);
    }

    if (CNEXT > 0) {
#pragma unroll
        for (int m = 0; m < CNEXT; ++m) {
            float s = sB1n[m];
#pragma unroll
            for (int o = 0; o < COUT; ++o) s = fmaf(v[o], sW1n[o * CNEXT + m], s);
            outbuf[(size_t)i * CNEXT + m] = s;
        }
    } else {
#pragma unroll
        for (int o = 0; o < COUT; ++o) outbuf[(size_t)i * COUT + o] = v[o];
    }
}

// ---------------------------------------------------------------------------
// Launch. Inputs (metadata order):
//  0 pos [N,3] f32 | 1 rgb (unused) | 2 batch [N] int
//  3 W1a[6,8] 4 b1a 5 W2a[8,8] 6 b2a | 7 W1b[11,16] 8 b1b 9 W2b[16,16] 10 b2b
// 11 W1c[19,32] 12 b1c 13 W2c[32,32] 14 b2c
// Output: concat [pos(3N) | feat(32N) | batch(N)] float32.
// ---------------------------------------------------------------------------
extern "C" void kernel_launch(void* const* d_in, const int* in_sizes, int n_in,
                              void* d_out, int out_size)
{
    const float* pos   = (const float*)d_in[0];
    const int*   batch = (const int*)d_in[2];
    const float* W1a = (const float*)d_in[3];
    const float* b1a = (const float*)d_in[4];
    const float* W2a = (const float*)d_in[5];
    const float* b2a = (const float*)d_in[6];
    const float* W1b = (const float*)d_in[7];
    const float* b1b = (const float*)d_in[8];
    const float* W2b = (const float*)d_in[9];
    const float* b2b = (const float*)d_in[10];
    const float* W1c = (const float*)d_in[11];
    const float* b1c = (const float*)d_in[12];
    const float* W2c = (const float*)d_in[13];
    const float* b2c = (const float*)d_in[14];

    float* out = (float*)d_out;

    void *pcnt, *pha, *phb, *phc;
    cudaGetSymbolAddress(&pcnt, g_cell_count);
    cudaGetSymbolAddress(&pha,  g_h0a);
    cudaGetSymbolAddress(&phb,  g_h0b);
    cudaGetSymbolAddress(&phc,  g_h0c);

    const int GB = NPTS / 128;  // 128 blocks of 128 threads

    cudaMemsetAsync(pcnt, 0, NCELL * sizeof(int));
    count_kernel<<<GB, 128>>>(pos, batch, out);
    scan_kernel<<<1, 1024>>>();
    scatter_kernel<<<GB, 128>>>(pos);
    query_kernel<<<GB, 128>>>(pos);
    pre_a_kernel<<<GB, 128>>>(pos, W1a, b1a);

    // pairA: layer-a aggregation -> celu -> fused x@W1b  (rel rows of W1a start at row 3)
    pair_kernel<8, 8, 16><<<GB, 128>>>((const float*)pha, pos,
                                       W1a + 3 * 8, W2a, b2a,
                                       W1b, b1b, (float*)phb);
    // pairB: layer-b aggregation -> celu -> fused x@W1c  (rel rows of W1b start at row 8)
    pair_kernel<16, 16, 32><<<GB, 128>>>((const float*)phb, pos,
                                         W1b + 8 * 16, W2b, b2b,
                                         W1c, b1c, (float*)phc);
    // pairC: layer-c aggregation -> celu -> final features (rel rows of W1c at row 16)
    pair_kernel<32, 32, 0><<<GB, 128>>>((const float*)phc, pos,
                                        W1c + 16 * 32, W2c, b2c,
                                        nullptr, nullptr, out + (size_t)NPTS * 3);
}

// round 3
// speedup vs baseline: 2.2709x; 1.2636x over previous
#include <cuda_runtime.h>
#include <math.h>

#define NPTS  16384
#define KMAX  64
#define R2    (1.0f / 256.0f)
#define NCELL 32768   // 8 clouds * 16^3 cells, cell edge = r = 1/16

// ---- scratch (static __device__ arrays; no allocation allowed) ----
__device__ int    g_cell_count[NCELL];
__device__ int    g_cell_start[NCELL + 1];
__device__ int    g_cell_fill[NCELL];
__device__ int    g_cell_of[NPTS];
__device__ float4 g_sorted[NPTS];          // x,y,z,|p|^2 cell-sorted
__device__ int    g_sorted_idx[NPTS];
__device__ int    g_nbr_idx[NPTS * KMAX];
__device__ float4 g_nbr_rel[NPTS * KMAX];  // pos_j - pos_i cached at query time
__device__ int    g_nbr_cnt[NPTS];
__device__ float4 g_h0a[NPTS * 2];         // per-layer  x@W1x + b1
__device__ float4 g_h0b[NPTS * 4];
__device__ float4 g_h0c[NPTS * 8];

__device__ __forceinline__ float celu1(float v) {
    return v > 0.0f ? v : expm1f(v);
}

// ---------------------------------------------------------------------------
// K1: cell assignment + histogram + pos/batch output copies + layer-a
// precompute h0a[i] = pos[i] @ W1a[0:3] + b1a.
// Output tuple layout: out = [pos(3N) | feat(32N) | batch(N)].
// ---------------------------------------------------------------------------
__global__ __launch_bounds__(128) void count_kernel(
    const float* __restrict__ pos, const int* __restrict__ batch,
    const float* __restrict__ W1a, const float* __restrict__ b1a,
    float* __restrict__ out)
{
    const int i = blockIdx.x * 128 + threadIdx.x;
    const float px = pos[3 * i + 0];
    const float py = pos[3 * i + 1];
    const float pz = pos[3 * i + 2];
    const int b = batch[i];

    out[3 * i + 0] = px;
    out[3 * i + 1] = py;
    out[3 * i + 2] = pz;
    out[(size_t)NPTS * 35 + i] = (float)b;

    int cx = min(15, max(0, (int)(px * 16.0f)));
    int cy = min(15, max(0, (int)(py * 16.0f)));
    int cz = min(15, max(0, (int)(pz * 16.0f)));
    int c = (b << 12) | (cz << 8) | (cy << 4) | cx;
    g_cell_of[i] = c;
    atomicAdd(&g_cell_count[c], 1);

    float h[8];
#pragma unroll
    for (int m = 0; m < 8; ++m) {
        float s = b1a[m];
        s = fmaf(px, W1a[0 * 8 + m], s);
        s = fmaf(py, W1a[1 * 8 + m], s);
        s = fmaf(pz, W1a[2 * 8 + m], s);
        h[m] = s;
    }
    g_h0a[(size_t)i * 2 + 0] = make_float4(h[0], h[1], h[2], h[3]);
    g_h0a[(size_t)i * 2 + 1] = make_float4(h[4], h[5], h[6], h[7]);
}

// ---------------------------------------------------------------------------
// K2: exclusive prefix sum over 32768 cells (1 block, 1024 thr, 32/thread).
// ---------------------------------------------------------------------------
__global__ __launch_bounds__(1024) void scan_kernel()
{
    __shared__ int sp[1024];
    const int t = threadIdx.x;
    const int base = t * 32;
    int local[32];
    int sum = 0;
#pragma unroll
    for (int k = 0; k < 32; ++k) { local[k] = g_cell_count[base + k]; sum += local[k]; }
    sp[t] = sum;
    __syncthreads();
    for (int off = 1; off < 1024; off <<= 1) {
        int v = (t >= off) ? sp[t - off] : 0;
        __syncthreads();
        sp[t] += v;
        __syncthreads();
    }
    int run = sp[t] - sum;
#pragma unroll
    for (int k = 0; k < 32; ++k) {
        g_cell_start[base + k] = run;
        g_cell_fill[base + k]  = run;
        run += local[k];
    }
    if (t == 1023) g_cell_start[NCELL] = run;
}

// ---------------------------------------------------------------------------
// K3: scatter points into cell-sorted order.
// ---------------------------------------------------------------------------
__global__ __launch_bounds__(128) void scatter_kernel(const float* __restrict__ pos)
{
    const int i = blockIdx.x * 128 + threadIdx.x;
    const float px = pos[3 * i + 0];
    const float py = pos[3 * i + 1];
    const float pz = pos[3 * i + 2];
    const int c = g_cell_of[i];
    const int p = atomicAdd(&g_cell_fill[c], 1);
    g_sorted[p] = make_float4(px, py, pz, px * px + py * py + pz * pz);
    g_sorted_idx[p] = i;
}

// ---------------------------------------------------------------------------
// K4: fused radius query + layer a.  4 lanes per point (consecutive lanes
// in a warp).  Lane r scans stencil runs r, r+4, r+8; accepted neighbors are
// recorded (idx + rel) and the layer-a message is folded into a per-lane
// partial max.  shfl_xor(width 4) reduce, lane-split epilogue:
//   v = celu(acc @ W2a + b2a);  h0b[i] = b1b + v @ W1b[0:8]  (next layer x-part)
// ---------------------------------------------------------------------------
__global__ __launch_bounds__(128) void qa_kernel(
    const float* __restrict__ pos,
    const float* __restrict__ W1rel,   // W1a rows 3..5  [3,8]
    const float* __restrict__ W2, const float* __restrict__ b2,   // [8,8],[8]
    const float* __restrict__ W1n, const float* __restrict__ b1n) // [8,16],[16]
{
    __shared__ float sW1r[3 * 8];
    __shared__ float sW2[8 * 8];
    __shared__ float sB2[8];
    __shared__ float sW1n[8 * 16];
    __shared__ float sB1n[16];
    __shared__ int   s_cnt[32];
    __shared__ float s_v[32][8];

    for (int k = threadIdx.x; k < 24;  k += 128) sW1r[k] = W1rel[k];
    for (int k = threadIdx.x; k < 64;  k += 128) sW2[k]  = W2[k];
    for (int k = threadIdx.x; k < 8;   k += 128) sB2[k]  = b2[k];
    for (int k = threadIdx.x; k < 128; k += 128) sW1n[k] = W1n[k];
    for (int k = threadIdx.x; k < 16;  k += 128) sB1n[k] = b1n[k];
    if (threadIdx.x < 32) s_cnt[threadIdx.x] = 0;
    __syncthreads();

    const int r = threadIdx.x & 3;      // lane within point-group
    const int p = threadIdx.x >> 2;     // point within block
    const int i = blockIdx.x * 32 + p;

    const float px = pos[3 * i + 0];
    const float py = pos[3 * i + 1];
    const float pz = pos[3 * i + 2];
    const float si = px * px + py * py + pz * pz;

    const int c  = g_cell_of[i];
    const int cx = c & 15, cy = (c >> 4) & 15, cz = (c >> 8) & 15;
    const int cloudbase = c & 0xF000;
    const int x0 = max(cx - 1, 0), x1 = min(cx + 1, 15);

    float acc[8];
#pragma unroll
    for (int m = 0; m < 8; ++m) acc[m] = -INFINITY;

    for (int run = r; run < 9; run += 4) {
        const int dz = run / 3 - 1, dy = run % 3 - 1;
        const int z = cz + dz, y = cy + dy;
        if ((unsigned)z > 15u || (unsigned)y > 15u) continue;
        const int rb = cloudbase | (z << 8) | (y << 4);
        const int js = g_cell_start[rb + x0];
        const int je = g_cell_start[rb + x1 + 1];
        for (int j = js; j < je; ++j) {
            const float4 q = g_sorted[j];
            const float dot = px * q.x + py * q.y + pz * q.z;
            const float d2  = si + q.w - 2.0f * dot;   // reference's formula
            if (d2 <= R2) {
                const int jo = g_sorted_idx[j];
                const float rx = q.x - px, ry = q.y - py, rz = q.z - pz;
                const int slot = atomicAdd(&s_cnt[p], 1);
                if (slot < KMAX) {
                    g_nbr_idx[(size_t)i * KMAX + slot] = jo;
                    g_nbr_rel[(size_t)i * KMAX + slot] = make_float4(rx, ry, rz, 0.0f);
                }
                const float4 h0 = g_h0a[(size_t)jo * 2 + 0];
                const float4 h1 = g_h0a[(size_t)jo * 2 + 1];
                const float hj[8] = {h0.x, h0.y, h0.z, h0.w, h1.x, h1.y, h1.z, h1.w};
#pragma unroll
                for (int m = 0; m < 8; ++m) {
                    float h = hj[m];
                    h = fmaf(rx, sW1r[0 * 8 + m], h);
                    h = fmaf(ry, sW1r[1 * 8 + m], h);
                    h = fmaf(rz, sW1r[2 * 8 + m], h);
                    acc[m] = fmaxf(acc[m], fmaxf(h, 0.0f));
                }
            }
        }
    }

    __syncwarp();
#pragma unroll
    for (int m = 0; m < 8; ++m) {
        acc[m] = fmaxf(acc[m], __shfl_xor_sync(0xffffffffu, acc[m], 1, 4));
        acc[m] = fmaxf(acc[m], __shfl_xor_sync(0xffffffffu, acc[m], 2, 4));
    }
    if (r == 0) g_nbr_cnt[i] = min(s_cnt[p], KMAX);

    // v[o], o = 2r..2r+1
#pragma unroll
    for (int oo = 0; oo < 2; ++oo) {
        const int o = r * 2 + oo;
        float s = sB2[o];
#pragma unroll
        for (int m = 0; m < 8; ++m) s = fmaf(acc[m], sW2[m * 8 + o], s);
        s_v[p][o] = celu1(s);
    }
    __syncwarp();

    float vv[8];
#pragma unroll
    for (int o = 0; o < 8; ++o) vv[o] = s_v[p][o];
    float o4[4];
#pragma unroll
    for (int mm = 0; mm < 4; ++mm) {
        const int m = r * 4 + mm;
        float s = sB1n[m];
#pragma unroll
        for (int o = 0; o < 8; ++o) s = fmaf(vv[o], sW1n[o * 16 + m], s);
        o4[mm] = s;
    }
    g_h0b[(size_t)i * 4 + r] = make_float4(o4[0], o4[1], o4[2], o4[3]);
}

// ---------------------------------------------------------------------------
// K5: layer b.  4 lanes per point, neighbors n = r, r+4, ...
//   acc = max relu(h0b[j] + rel@W1rel);  v = celu(acc@W2b + b2b);
//   h0c[i] = b1c + v @ W1c[0:16]
// ---------------------------------------------------------------------------
__global__ __launch_bounds__(128) void pairB_kernel(
    const float* __restrict__ W1rel,   // W1b rows 8..10 [3,16]
    const float* __restrict__ W2, const float* __restrict__ b2,   // [16,16],[16]
    const float* __restrict__ W1n, const float* __restrict__ b1n) // [16,32],[32]
{
    __shared__ float sW1r[3 * 16];
    __shared__ float sW2[16 * 16];
    __shared__ float sB2[16];
    __shared__ float sW1n[16 * 32];
    __shared__ float sB1n[32];
    __shared__ float s_v[32][16];

    for (int k = threadIdx.x; k < 48;  k += 128) sW1r[k] = W1rel[k];
    for (int k = threadIdx.x; k < 256; k += 128) sW2[k]  = W2[k];
    for (int k = threadIdx.x; k < 16;  k += 128) sB2[k]  = b2[k];
    for (int k = threadIdx.x; k < 512; k += 128) sW1n[k] = W1n[k];
    for (int k = threadIdx.x; k < 32;  k += 128) sB1n[k] = b1n[k];
    __syncthreads();

    const int r = threadIdx.x & 3;
    const int p = threadIdx.x >> 2;
    const int i = blockIdx.x * 32 + p;
    const int cnt = g_nbr_cnt[i];

    float acc[16];
#pragma unroll
    for (int m = 0; m < 16; ++m) acc[m] = -INFINITY;

    for (int n = r; n < cnt; n += 4) {
        const float4 rel = g_nbr_rel[(size_t)i * KMAX + n];
        const int j = g_nbr_idx[(size_t)i * KMAX + n];
        float hj[16];
#pragma unroll
        for (int q = 0; q < 4; ++q) {
            const float4 h = g_h0b[(size_t)j * 4 + q];
            hj[4 * q + 0] = h.x; hj[4 * q + 1] = h.y;
            hj[4 * q + 2] = h.z; hj[4 * q + 3] = h.w;
        }
#pragma unroll
        for (int m = 0; m < 16; ++m) {
            float h = hj[m];
            h = fmaf(rel.x, sW1r[0 * 16 + m], h);
            h = fmaf(rel.y, sW1r[1 * 16 + m], h);
            h = fmaf(rel.z, sW1r[2 * 16 + m], h);
            acc[m] = fmaxf(acc[m], fmaxf(h, 0.0f));
        }
    }

    __syncwarp();
#pragma unroll
    for (int m = 0; m < 16; ++m) {
        acc[m] = fmaxf(acc[m], __shfl_xor_sync(0xffffffffu, acc[m], 1, 4));
        acc[m] = fmaxf(acc[m], __shfl_xor_sync(0xffffffffu, acc[m], 2, 4));
    }

#pragma unroll
    for (int oo = 0; oo < 4; ++oo) {
        const int o = r * 4 + oo;
        float s = sB2[o];
#pragma unroll
        for (int m = 0; m < 16; ++m) s = fmaf(acc[m], sW2[m * 16 + o], s);
        s_v[p][o] = celu1(s);
    }
    __syncwarp();

    float vv[16];
#pragma unroll
    for (int o = 0; o < 16; ++o) vv[o] = s_v[p][o];
    float o8[8];
#pragma unroll
    for (int mm = 0; mm < 8; ++mm) {
        const int m = r * 8 + mm;
        float s = sB1n[m];
#pragma unroll
        for (int o = 0; o < 16; ++o) s = fmaf(vv[o], sW1n[o * 32 + m], s);
        o8[mm] = s;
    }
    g_h0c[(size_t)i * 8 + r * 2 + 0] = make_float4(o8[0], o8[1], o8[2], o8[3]);
    g_h0c[(size_t)i * 8 + r * 2 + 1] = make_float4(o8[4], o8[5], o8[6], o8[7]);
}

// ---------------------------------------------------------------------------
// K6: layer c -> final features.
// ---------------------------------------------------------------------------
__global__ __launch_bounds__(128) void pairC_kernel(
    const float* __restrict__ W1rel,   // W1c rows 16..18 [3,32]
    const float* __restrict__ W2, const float* __restrict__ b2,   // [32,32],[32]
    float* __restrict__ outfeat)       // out + 3N
{
    __shared__ float sW1r[3 * 32];
    __shared__ float sW2[32 * 32];
    __shared__ float sB2[32];

    for (int k = threadIdx.x; k < 96;   k += 128) sW1r[k] = W1rel[k];
    for (int k = threadIdx.x; k < 1024; k += 128) sW2[k]  = W2[k];
    for (int k = threadIdx.x; k < 32;   k += 128) sB2[k]  = b2[k];
    __syncthreads();

    const int r = threadIdx.x & 3;
    const int p = threadIdx.x >> 2;
    const int i = blockIdx.x * 32 + p;
    const int cnt = g_nbr_cnt[i];

    float acc[32];
#pragma unroll
    for (int m = 0; m < 32; ++m) acc[m] = -INFINITY;

    for (int n = r; n < cnt; n += 4) {
        const float4 rel = g_nbr_rel[(size_t)i * KMAX + n];
        const int j = g_nbr_idx[(size_t)i * KMAX + n];
        float hj[32];
#pragma unroll
        for (int q = 0; q < 8; ++q) {
            const float4 h = g_h0c[(size_t)j * 8 + q];
            hj[4 * q + 0] = h.x; hj[4 * q + 1] = h.y;
            hj[4 * q + 2] = h.z; hj[4 * q + 3] = h.w;
        }
#pragma unroll
        for (int m = 0; m < 32; ++m) {
            float h = hj[m];
            h = fmaf(rel.x, sW1r[0 * 32 + m], h);
            h = fmaf(rel.y, sW1r[1 * 32 + m], h);
            h = fmaf(rel.z, sW1r[2 * 32 + m], h);
            acc[m] = fmaxf(acc[m], fmaxf(h, 0.0f));
        }
    }

    __syncwarp();
#pragma unroll
    for (int m = 0; m < 32; ++m) {
        acc[m] = fmaxf(acc[m], __shfl_xor_sync(0xffffffffu, acc[m], 1, 4));
        acc[m] = fmaxf(acc[m], __shfl_xor_sync(0xffffffffu, acc[m], 2, 4));
    }

    float o8[8];
#pragma unroll
    for (int oo = 0; oo < 8; ++oo) {
        const int o = r * 8 + oo;
        float s = sB2[o];
#pragma unroll
        for (int m = 0; m < 32; ++m) s = fmaf(acc[m], sW2[m * 32 + o], s);
        o8[oo] = celu1(s);
    }
    float4* dst = reinterpret_cast<float4*>(outfeat + (size_t)i * 32 + r * 8);
    dst[0] = make_float4(o8[0], o8[1], o8[2], o8[3]);
    dst[1] = make_float4(o8[4], o8[5], o8[6], o8[7]);
}

// ---------------------------------------------------------------------------
// Launch. Inputs: 0 pos | 1 rgb (unused) | 2 batch |
//  3 W1a[6,8] 4 b1a 5 W2a 6 b2a | 7 W1b[11,16] 8 b1b 9 W2b 10 b2b
// 11 W1c[19,32] 12 b1c 13 W2c 14 b2c
// Output: [pos(3N) | feat(32N) | batch(N)] float32.
// ---------------------------------------------------------------------------
extern "C" void kernel_launch(void* const* d_in, const int* in_sizes, int n_in,
                              void* d_out, int out_size)
{
    const float* pos   = (const float*)d_in[0];
    const int*   batch = (const int*)d_in[2];
    const float* W1a = (const float*)d_in[3];
    const float* b1a = (const float*)d_in[4];
    const float* W2a = (const float*)d_in[5];
    const float* b2a = (const float*)d_in[6];
    const float* W1b = (const float*)d_in[7];
    const float* b1b = (const float*)d_in[8];
    const float* W2b = (const float*)d_in[9];
    const float* b2b = (const float*)d_in[10];
    const float* W1c = (const float*)d_in[11];
    const float* b1c = (const float*)d_in[12];
    const float* W2c = (const float*)d_in[13];
    const float* b2c = (const float*)d_in[14];

    float* out = (float*)d_out;

    void* pcnt = nullptr;
    cudaGetSymbolAddress(&pcnt, g_cell_count);

    const int GB  = NPTS / 128;      // 128 blocks (1 thread / point)
    const int GB4 = NPTS * 4 / 128;  // 512 blocks (4 threads / point)

    cudaMemsetAsync(pcnt, 0, NCELL * sizeof(int));
    count_kernel<<<GB, 128>>>(pos, batch, W1a, b1a, out);
    scan_kernel<<<1, 1024>>>();
    scatter_kernel<<<GB, 128>>>(pos);
    qa_kernel<<<GB4, 128>>>(pos, W1a + 3 * 8, W2a, b2a, W1b, b1b);
    pairB_kernel<<<GB4, 128>>>(W1b + 8 * 16, W2b, b2b, W1c, b1c);
    pairC_kernel<<<GB4, 128>>>(W1c + 16 * 32, W2c, b2c, out + (size_t)NPTS * 3);
}

// round 4
// speedup vs baseline: 4.1331x; 1.8200x over previous
#include <cuda_runtime.h>
#include <math.h>

#define NPTS  16384
#define KMAX  64
#define R2    (1.0f / 256.0f)
#define NCELL 32768   // 8 clouds * 16^3 cells, cell edge = r = 1/16
#define NBLK  512     // persistent grid: 512 blocks x 128 threads = 65536 = 4*NPTS

// ---- scratch (static __device__ arrays; no allocation allowed) ----
__device__ int    g_cell_count[NCELL];
__device__ int    g_cell_start[NCELL + 1];
__device__ int    g_cell_fill[NCELL];
__device__ int    g_cell_of[NPTS];
__device__ float4 g_sorted[NPTS];          // x,y,z,|p|^2 cell-sorted
__device__ int    g_sorted_idx[NPTS];
__device__ int    g_nbr_idx[NPTS * KMAX];
__device__ float4 g_nbr_rel[NPTS * KMAX];  // pos_j - pos_i cached at query time
__device__ int    g_nbr_cnt[NPTS];
__device__ float4 g_h0a[NPTS * 2];         // per-layer  x@W1x + b1
__device__ float4 g_h0b[NPTS * 4];
__device__ float4 g_h0c[NPTS * 8];
__device__ int    g_block_sum[NBLK];
__device__ int    g_block_pref[NBLK];

// ---- software grid barrier (all NBLK blocks guaranteed co-resident) ----
__device__ int          g_bar_count = 0;
__device__ volatile int g_bar_gen   = 0;

__device__ __forceinline__ void grid_barrier() {
    __syncthreads();
    if (threadIdx.x == 0) {
        __threadfence();                       // release: publish this block's writes
        const int gen = g_bar_gen;
        if (atomicAdd(&g_bar_count, 1) == NBLK - 1) {
            g_bar_count = 0;
            __threadfence();
            g_bar_gen = gen + 1;               // release everyone
        } else {
            while (g_bar_gen == gen) __nanosleep(40);
        }
        __threadfence();                       // acquire
    }
    __syncthreads();
}

__device__ __forceinline__ float celu1(float v) {
    return v > 0.0f ? v : expm1f(v);
}

// ---------------------------------------------------------------------------
// One persistent kernel: build grid -> scan -> scatter -> query+A -> B -> C.
// Output tuple layout: out = [pos(3N) | feat(32N) | batch(N)].
// ---------------------------------------------------------------------------
__global__ __launch_bounds__(128, 4) void fused_kernel(
    const float* __restrict__ pos, const int* __restrict__ batch,
    const float* __restrict__ W1a, const float* __restrict__ b1a,
    const float* __restrict__ W2a, const float* __restrict__ b2a,
    const float* __restrict__ W1b, const float* __restrict__ b1b,
    const float* __restrict__ W2b, const float* __restrict__ b2b,
    const float* __restrict__ W1c, const float* __restrict__ b1c,
    const float* __restrict__ W2c, const float* __restrict__ b2c,
    float* __restrict__ out)
{
    // ---- shared: all weights staged once + per-phase workspaces ----
    __shared__ float sWar[24],  sW2a[64],   sB2a[8],  sWbx[128], sB1b[16];
    __shared__ float sWbr[48],  sW2b[256],  sB2b[16], sWcx[512], sB1c[32];
    __shared__ float sWcr[96],  sW2c[1024], sB2c[32];
    __shared__ int   s_cells[64];
    __shared__ int   s_red[128];
    __shared__ int   s_cnt[32];
    __shared__ float s_v[32][16];

    const int tid  = threadIdx.x;
    const int blk  = blockIdx.x;
    const int gtid = blk * 128 + tid;

    // stage weights (once)
    for (int k = tid; k < 24;   k += 128) sWar[k] = W1a[3 * 8 + k];   // rel rows of W1a
    for (int k = tid; k < 64;   k += 128) sW2a[k] = W2a[k];
    for (int k = tid; k < 8;    k += 128) sB2a[k] = b2a[k];
    for (int k = tid; k < 128;  k += 128) sWbx[k] = W1b[k];           // x rows of W1b
    for (int k = tid; k < 16;   k += 128) sB1b[k] = b1b[k];
    for (int k = tid; k < 48;   k += 128) sWbr[k] = W1b[8 * 16 + k];  // rel rows of W1b
    for (int k = tid; k < 256;  k += 128) sW2b[k] = W2b[k];
    for (int k = tid; k < 16;   k += 128) sB2b[k] = b2b[k];
    for (int k = tid; k < 512;  k += 128) sWcx[k] = W1c[k];           // x rows of W1c
    for (int k = tid; k < 32;   k += 128) sB1c[k] = b1c[k];
    for (int k = tid; k < 96;   k += 128) sWcr[k] = W1c[16 * 32 + k]; // rel rows of W1c
    for (int k = tid; k < 1024; k += 128) sW2c[k] = W2c[k];
    for (int k = tid; k < 32;   k += 128) sB2c[k] = b2c[k];

    // ---- phase 0: clear histogram ----
    if (gtid < NCELL) g_cell_count[gtid] = 0;
    grid_barrier();

    // ---- phase 1: cell assign + histogram + output copies + h0a ----
    if (gtid < NPTS) {
        const int i = gtid;
        const float px = pos[3 * i + 0];
        const float py = pos[3 * i + 1];
        const float pz = pos[3 * i + 2];
        const int bb = batch[i];

        out[3 * i + 0] = px;
        out[3 * i + 1] = py;
        out[3 * i + 2] = pz;
        out[(size_t)NPTS * 35 + i] = (float)bb;

        int cx = min(15, max(0, (int)(px * 16.0f)));
        int cy = min(15, max(0, (int)(py * 16.0f)));
        int cz = min(15, max(0, (int)(pz * 16.0f)));
        const int c = (bb << 12) | (cz << 8) | (cy << 4) | cx;
        g_cell_of[i] = c;
        atomicAdd(&g_cell_count[c], 1);

        float h[8];
#pragma unroll
        for (int m = 0; m < 8; ++m) {
            float s = b1a[m];
            s = fmaf(px, W1a[0 * 8 + m], s);
            s = fmaf(py, W1a[1 * 8 + m], s);
            s = fmaf(pz, W1a[2 * 8 + m], s);
            h[m] = s;
        }
        g_h0a[(size_t)i * 2 + 0] = make_float4(h[0], h[1], h[2], h[3]);
        g_h0a[(size_t)i * 2 + 1] = make_float4(h[4], h[5], h[6], h[7]);
    }
    grid_barrier();

    // ---- phase 2: per-block sum of 64 cells (cells cached in smem) ----
    {
        const int base = blk * 64;
        int v = 0;
        if (tid < 64) { v = g_cell_count[base + tid]; s_cells[tid] = v; }
        s_red[tid] = v;
        __syncthreads();
#pragma unroll
        for (int off = 64; off > 0; off >>= 1) {
            if (tid < off) s_red[tid] += s_red[tid + off];
            __syncthreads();
        }
        if (tid == 0) g_block_sum[blk] = s_red[0];
    }
    grid_barrier();

    // ---- phase 3: block 0 scans 512 block sums ----
    if (blk == 0) {
        int v0 = g_block_sum[tid * 4 + 0];
        int v1 = g_block_sum[tid * 4 + 1];
        int v2 = g_block_sum[tid * 4 + 2];
        int v3 = g_block_sum[tid * 4 + 3];
        const int sum = v0 + v1 + v2 + v3;
        s_red[tid] = sum;
        __syncthreads();
        for (int off = 1; off < 128; off <<= 1) {
            int v = (tid >= off) ? s_red[tid - off] : 0;
            __syncthreads();
            s_red[tid] += v;
            __syncthreads();
        }
        int run = s_red[tid] - sum;
        g_block_pref[tid * 4 + 0] = run; run += v0;
        g_block_pref[tid * 4 + 1] = run; run += v1;
        g_block_pref[tid * 4 + 2] = run; run += v2;
        g_block_pref[tid * 4 + 3] = run;
        if (tid == 127) g_cell_start[NCELL] = s_red[127];
    }
    grid_barrier();

    // ---- phase 4: per-block 64-cell exclusive prefix ----
    {
        const int base = blk * 64;
        const int c = (tid < 64) ? s_cells[tid] : 0;
        s_red[tid] = c;
        __syncthreads();
        for (int off = 1; off < 64; off <<= 1) {
            int v = 0;
            if (tid < 64 && tid >= off) v = s_red[tid - off];
            __syncthreads();
            if (tid < 64) s_red[tid] += v;
            __syncthreads();
        }
        if (tid < 64) {
            const int st = g_block_pref[blk] + s_red[tid] - c;
            g_cell_start[base + tid] = st;
            g_cell_fill[base + tid]  = st;
        }
    }
    grid_barrier();

    // ---- phase 5: scatter into cell-sorted order ----
    if (gtid < NPTS) {
        const int i = gtid;
        const float px = pos[3 * i + 0];
        const float py = pos[3 * i + 1];
        const float pz = pos[3 * i + 2];
        const int c = g_cell_of[i];
        const int p = atomicAdd(&g_cell_fill[c], 1);
        g_sorted[p] = make_float4(px, py, pz, px * px + py * py + pz * pz);
        g_sorted_idx[p] = i;
    }
    grid_barrier();

    // common lane decomposition for pair phases: 4 lanes per point
    const int r = tid & 3;
    const int p = tid >> 2;
    const int i = blk * 32 + p;

    // ---- phase 6: radius query fused with layer a ----
    {
        if (tid < 32) s_cnt[tid] = 0;
        __syncthreads();

        const float px = pos[3 * i + 0];
        const float py = pos[3 * i + 1];
        const float pz = pos[3 * i + 2];
        const float si = px * px + py * py + pz * pz;

        const int c  = g_cell_of[i];
        const int cx = c & 15, cy = (c >> 4) & 15, cz = (c >> 8) & 15;
        const int cloudbase = c & 0xF000;
        const int x0 = max(cx - 1, 0), x1 = min(cx + 1, 15);

        float acc[8];
#pragma unroll
        for (int m = 0; m < 8; ++m) acc[m] = -INFINITY;

        for (int run = r; run < 9; run += 4) {
            const int dz = run / 3 - 1, dy = run % 3 - 1;
            const int z = cz + dz, y = cy + dy;
            if ((unsigned)z > 15u || (unsigned)y > 15u) continue;
            const int rb = cloudbase | (z << 8) | (y << 4);
            const int js = g_cell_start[rb + x0];
            const int je = g_cell_start[rb + x1 + 1];
            for (int j = js; j < je; ++j) {
                const float4 q = g_sorted[j];
                const float dot = px * q.x + py * q.y + pz * q.z;
                const float d2  = si + q.w - 2.0f * dot;   // reference's formula
                if (d2 <= R2) {
                    const int jo = g_sorted_idx[j];
                    const float rx = q.x - px, ry = q.y - py, rz = q.z - pz;
                    const int slot = atomicAdd(&s_cnt[p], 1);
                    if (slot < KMAX) {
                        g_nbr_idx[(size_t)i * KMAX + slot] = jo;
                        g_nbr_rel[(size_t)i * KMAX + slot] = make_float4(rx, ry, rz, 0.0f);
                    }
                    const float4 h0 = g_h0a[(size_t)jo * 2 + 0];
                    const float4 h1 = g_h0a[(size_t)jo * 2 + 1];
                    const float hj[8] = {h0.x, h0.y, h0.z, h0.w, h1.x, h1.y, h1.z, h1.w};
#pragma unroll
                    for (int m = 0; m < 8; ++m) {
                        float h = hj[m];
                        h = fmaf(rx, sWar[0 * 8 + m], h);
                        h = fmaf(ry, sWar[1 * 8 + m], h);
                        h = fmaf(rz, sWar[2 * 8 + m], h);
                        acc[m] = fmaxf(acc[m], fmaxf(h, 0.0f));
                    }
                }
            }
        }

        __syncwarp();
#pragma unroll
        for (int m = 0; m < 8; ++m) {
            acc[m] = fmaxf(acc[m], __shfl_xor_sync(0xffffffffu, acc[m], 1, 4));
            acc[m] = fmaxf(acc[m], __shfl_xor_sync(0xffffffffu, acc[m], 2, 4));
        }
        if (r == 0) g_nbr_cnt[i] = min(s_cnt[p], KMAX);

#pragma unroll
        for (int oo = 0; oo < 2; ++oo) {
            const int o = r * 2 + oo;
            float s = sB2a[o];
#pragma unroll
            for (int m = 0; m < 8; ++m) s = fmaf(acc[m], sW2a[m * 8 + o], s);
            s_v[p][o] = celu1(s);
        }
        __syncwarp();

        float vv[8];
#pragma unroll
        for (int o = 0; o < 8; ++o) vv[o] = s_v[p][o];
        float o4[4];
#pragma unroll
        for (int mm = 0; mm < 4; ++mm) {
            const int m = r * 4 + mm;
            float s = sB1b[m];
#pragma unroll
            for (int o = 0; o < 8; ++o) s = fmaf(vv[o], sWbx[o * 16 + m], s);
            o4[mm] = s;
        }
        g_h0b[(size_t)i * 4 + r] = make_float4(o4[0], o4[1], o4[2], o4[3]);
    }
    grid_barrier();

    // ---- phase 7: layer b ----
    {
        const int cnt = g_nbr_cnt[i];
        float acc[16];
#pragma unroll
        for (int m = 0; m < 16; ++m) acc[m] = -INFINITY;

        for (int n = r; n < cnt; n += 4) {
            const float4 rel = g_nbr_rel[(size_t)i * KMAX + n];
            const int j = g_nbr_idx[(size_t)i * KMAX + n];
            float hj[16];
#pragma unroll
            for (int q = 0; q < 4; ++q) {
                const float4 h = g_h0b[(size_t)j * 4 + q];
                hj[4 * q + 0] = h.x; hj[4 * q + 1] = h.y;
                hj[4 * q + 2] = h.z; hj[4 * q + 3] = h.w;
            }
#pragma unroll
            for (int m = 0; m < 16; ++m) {
                float h = hj[m];
                h = fmaf(rel.x, sWbr[0 * 16 + m], h);
                h = fmaf(rel.y, sWbr[1 * 16 + m], h);
                h = fmaf(rel.z, sWbr[2 * 16 + m], h);
                acc[m] = fmaxf(acc[m], fmaxf(h, 0.0f));
            }
        }

        __syncwarp();
#pragma unroll
        for (int m = 0; m < 16; ++m) {
            acc[m] = fmaxf(acc[m], __shfl_xor_sync(0xffffffffu, acc[m], 1, 4));
            acc[m] = fmaxf(acc[m], __shfl_xor_sync(0xffffffffu, acc[m], 2, 4));
        }

#pragma unroll
        for (int oo = 0; oo < 4; ++oo) {
            const int o = r * 4 + oo;
            float s = sB2b[o];
#pragma unroll
            for (int m = 0; m < 16; ++m) s = fmaf(acc[m], sW2b[m * 16 + o], s);
            s_v[p][o] = celu1(s);
        }
        __syncwarp();

        float vv[16];
#pragma unroll
        for (int o = 0; o < 16; ++o) vv[o] = s_v[p][o];
        float o8[8];
#pragma unroll
        for (int mm = 0; mm < 8; ++mm) {
            const int m = r * 8 + mm;
            float s = sB1c[m];
#pragma unroll
            for (int o = 0; o < 16; ++o) s = fmaf(vv[o], sWcx[o * 32 + m], s);
            o8[mm] = s;
        }
        g_h0c[(size_t)i * 8 + r * 2 + 0] = make_float4(o8[0], o8[1], o8[2], o8[3]);
        g_h0c[(size_t)i * 8 + r * 2 + 1] = make_float4(o8[4], o8[5], o8[6], o8[7]);
    }
    grid_barrier();

    // ---- phase 8: layer c -> final features ----
    {
        const int cnt = g_nbr_cnt[i];
        float acc[32];
#pragma unroll
        for (int m = 0; m < 32; ++m) acc[m] = -INFINITY;

        for (int n = r; n < cnt; n += 4) {
            const float4 rel = g_nbr_rel[(size_t)i * KMAX + n];
            const int j = g_nbr_idx[(size_t)i * KMAX + n];
            float hj[32];
#pragma unroll
            for (int q = 0; q < 8; ++q) {
                const float4 h = g_h0c[(size_t)j * 8 + q];
                hj[4 * q + 0] = h.x; hj[4 * q + 1] = h.y;
                hj[4 * q + 2] = h.z; hj[4 * q + 3] = h.w;
            }
#pragma unroll
            for (int m = 0; m < 32; ++m) {
                float h = hj[m];
                h = fmaf(rel.x, sWcr[0 * 32 + m], h);
                h = fmaf(rel.y, sWcr[1 * 32 + m], h);
                h = fmaf(rel.z, sWcr[2 * 32 + m], h);
                acc[m] = fmaxf(acc[m], fmaxf(h, 0.0f));
            }
        }

        __syncwarp();
#pragma unroll
        for (int m = 0; m < 32; ++m) {
            acc[m] = fmaxf(acc[m], __shfl_xor_sync(0xffffffffu, acc[m], 1, 4));
            acc[m] = fmaxf(acc[m], __shfl_xor_sync(0xffffffffu, acc[m], 2, 4));
        }

        float o8[8];
#pragma unroll
        for (int oo = 0; oo < 8; ++oo) {
            const int o = r * 8 + oo;
            float s = sB2c[o];
#pragma unroll
            for (int m = 0; m < 32; ++m) s = fmaf(acc[m], sW2c[m * 32 + o], s);
            o8[oo] = celu1(s);
        }
        float4* dst = reinterpret_cast<float4*>(out + (size_t)NPTS * 3 + (size_t)i * 32 + r * 8);
        dst[0] = make_float4(o8[0], o8[1], o8[2], o8[3]);
        dst[1] = make_float4(o8[4], o8[5], o8[6], o8[7]);
    }
}

// ---------------------------------------------------------------------------
// Launch. Inputs: 0 pos | 1 rgb (unused) | 2 batch |
//  3 W1a[6,8] 4 b1a 5 W2a 6 b2a | 7 W1b[11,16] 8 b1b 9 W2b 10 b2b
// 11 W1c[19,32] 12 b1c 13 W2c 14 b2c
// Output: [pos(3N) | feat(32N) | batch(N)] float32.
// ---------------------------------------------------------------------------
extern "C" void kernel_launch(void* const* d_in, const int* in_sizes, int n_in,
                              void* d_out, int out_size)
{
    const float* pos   = (const float*)d_in[0];
    const int*   batch = (const int*)d_in[2];

    fused_kernel<<<NBLK, 128>>>(
        pos, batch,
        (const float*)d_in[3],  (const float*)d_in[4],
        (const float*)d_in[5],  (const float*)d_in[6],
        (const float*)d_in[7],  (const float*)d_in[8],
        (const float*)d_in[9],  (const float*)d_in[10],
        (const float*)d_in[11], (const float*)d_in[12],
        (const float*)d_in[13], (const float*)d_in[14],
        (float*)d_out);
}

// round 5
// speedup vs baseline: 6.6073x; 1.5987x over previous
#include <cuda_runtime.h>
#include <math.h>

#define NPTS  16384
#define R2    (1.0f / 256.0f)
#define NCELL 32768         // 8 clouds * 16^3, cell edge = r = 1/16
#define NBLK  512
#define NTHR  256           // 8 lanes per point, 32 points per block
#define CAPB  16            // bucket slots per cell (lambda ~0.5)
#define CAPN  32            // per-point neighbor capacity (lambda ~2.1)

// ---- scratch (static __device__; no allocation allowed) ----
__device__ int    g_cell_cnt[NCELL];            // zero-init; re-cleared each run
__device__ float4 g_bucket_pos[NCELL * CAPB];   // x,y,z,|p|^2
__device__ int    g_bucket_idx[NCELL * CAPB];
__device__ float  g_h0a[NPTS * 8];              // per-layer  x@W1x + b1
__device__ float  g_h0b[NPTS * 16];
__device__ float  g_h0c[NPTS * 32];

// ---- software grid barrier (all NBLK blocks co-resident by launch_bounds) ----
__device__ int          g_bar_count = 0;
__device__ volatile int g_bar_gen   = 0;

__device__ __forceinline__ void grid_barrier() {
    __syncthreads();
    if (threadIdx.x == 0) {
        __threadfence();
        const int gen = g_bar_gen;
        if (atomicAdd(&g_bar_count, 1) == NBLK - 1) {
            g_bar_count = 0;
            __threadfence();
            g_bar_gen = gen + 1;
        } else {
            while (g_bar_gen == gen) __nanosleep(32);
        }
        __threadfence();
    }
    __syncthreads();
}

__device__ __forceinline__ float celu1(float v) {
    return v > 0.0f ? v : expm1f(v);
}

// ---------------------------------------------------------------------------
// One persistent kernel, 3 grid barriers:
//   P1 bucket-build + h0a + output copies | P2 query (+) layer a | P3 layer b
//   | P4 layer c.  8 lanes per point; neighbor lists cached in smem.
// Output tuple layout: out = [pos(3N) | feat(32N) | batch(N)].
// ---------------------------------------------------------------------------
__global__ __launch_bounds__(NTHR, 4) void fused_kernel(
    const float* __restrict__ pos, const int* __restrict__ batch,
    const float* __restrict__ W1a, const float* __restrict__ b1a,
    const float* __restrict__ W2a, const float* __restrict__ b2a,
    const float* __restrict__ W1b, const float* __restrict__ b1b,
    const float* __restrict__ W2b, const float* __restrict__ b2b,
    const float* __restrict__ W1c, const float* __restrict__ b1c,
    const float* __restrict__ W2c, const float* __restrict__ b2c,
    float* __restrict__ out)
{
    // weights in smem (broadcast LDS)
    __shared__ float sWar[24],  sW2a[64],   sB2a[8],  sWbx[128], sB1b[16];
    __shared__ float sWbr[48],  sW2b[256],  sB2b[16], sWcx[512], sB1c[32];
    __shared__ float sWcr[96],  sW2c[1024], sB2c[32];
    __shared__ int    s_cnt[32];
    __shared__ int    s_nidx[32 * CAPN];
    __shared__ float4 s_nrel[32 * CAPN];

    const int tid = threadIdx.x;
    const int blk = blockIdx.x;
    const int gtid = blk * NTHR + tid;
    const int r = tid & 7;        // lane within point-group (0..7)
    const int p = tid >> 3;       // point within block (0..31)
    const int i = blk * 32 + p;   // global point id

    for (int k = tid; k < 24;   k += NTHR) sWar[k] = W1a[24 + k];        // rel rows
    for (int k = tid; k < 64;   k += NTHR) sW2a[k] = W2a[k];
    for (int k = tid; k < 8;    k += NTHR) sB2a[k] = b2a[k];
    for (int k = tid; k < 128;  k += NTHR) sWbx[k] = W1b[k];             // x rows
    for (int k = tid; k < 16;   k += NTHR) sB1b[k] = b1b[k];
    for (int k = tid; k < 48;   k += NTHR) sWbr[k] = W1b[128 + k];       // rel rows
    for (int k = tid; k < 256;  k += NTHR) sW2b[k] = W2b[k];
    for (int k = tid; k < 16;   k += NTHR) sB2b[k] = b2b[k];
    for (int k = tid; k < 512;  k += NTHR) sWcx[k] = W1c[k];             // x rows
    for (int k = tid; k < 32;   k += NTHR) sB1c[k] = b1c[k];
    for (int k = tid; k < 96;   k += NTHR) sWcr[k] = W1c[512 + k];       // rel rows
    for (int k = tid; k < 1024; k += NTHR) sW2c[k] = W2c[k];
    for (int k = tid; k < 32;   k += NTHR) sB2c[k] = b2c[k];

    // ---- P1: bucket insert + h0a + output pos/batch copies ----
    const float px = pos[3 * i + 0];
    const float py = pos[3 * i + 1];
    const float pz = pos[3 * i + 2];
    const float si = px * px + py * py + pz * pz;
    const int bb = batch[i];
    const int cx0 = min(15, max(0, (int)(px * 16.0f)));
    const int cy0 = min(15, max(0, (int)(py * 16.0f)));
    const int cz0 = min(15, max(0, (int)(pz * 16.0f)));
    const int c = (bb << 12) | (cz0 << 8) | (cy0 << 4) | cx0;

    if (r == 0) {
        out[3 * i + 0] = px;
        out[3 * i + 1] = py;
        out[3 * i + 2] = pz;
        out[(size_t)NPTS * 35 + i] = (float)bb;
    } else if (r == 1) {
        const int slot = atomicAdd(&g_cell_cnt[c], 1);
        if (slot < CAPB) {
            g_bucket_pos[c * CAPB + slot] = make_float4(px, py, pz, si);
            g_bucket_idx[c * CAPB + slot] = i;
        }
    }
    {   // h0a channel r = pos @ W1a[0:3][:,r] + b1a[r]
        float s = b1a[r];
        s = fmaf(px, W1a[0 * 8 + r], s);
        s = fmaf(py, W1a[1 * 8 + r], s);
        s = fmaf(pz, W1a[2 * 8 + r], s);
        g_h0a[i * 8 + r] = s;
    }
    grid_barrier();

    // ---- P2: radius query (27-cell stencil, lanes split cells) + layer a ----
    int cnt;
    {
        if (r == 0) s_cnt[p] = 0;
        __syncwarp();

        const int cb = c & 0xF000;
        float acc[8];
#pragma unroll
        for (int m = 0; m < 8; ++m) acc[m] = -INFINITY;

        for (int k = r; k < 27; k += 8) {
            const int z = cz0 + k / 9 - 1;
            const int y = cy0 + (k / 3) % 3 - 1;
            const int x = cx0 + k % 3 - 1;
            if ((unsigned)(z | y | x) > 15u) continue;
            const int cell = cb | (z << 8) | (y << 4) | x;
            const int n = min(g_cell_cnt[cell], CAPB);
            const int base = cell * CAPB;
            for (int e = 0; e < n; ++e) {
                const float4 q = g_bucket_pos[base + e];
                const float dot = px * q.x + py * q.y + pz * q.z;
                const float d2  = si + q.w - 2.0f * dot;   // reference's formula
                if (d2 <= R2) {
                    const int jo = g_bucket_idx[base + e];
                    const float rx = q.x - px, ry = q.y - py, rz = q.z - pz;
                    const int slot = atomicAdd(&s_cnt[p], 1);
                    if (slot < CAPN) {
                        s_nidx[p * CAPN + slot] = jo;
                        s_nrel[p * CAPN + slot] = make_float4(rx, ry, rz, 0.0f);
                    }
                    const float4 h0 = *(const float4*)&g_h0a[jo * 8 + 0];
                    const float4 h1 = *(const float4*)&g_h0a[jo * 8 + 4];
                    const float hj[8] = {h0.x, h0.y, h0.z, h0.w,
                                         h1.x, h1.y, h1.z, h1.w};
#pragma unroll
                    for (int m = 0; m < 8; ++m) {
                        float h = hj[m];
                        h = fmaf(rx, sWar[0 * 8 + m], h);
                        h = fmaf(ry, sWar[1 * 8 + m], h);
                        h = fmaf(rz, sWar[2 * 8 + m], h);
                        acc[m] = fmaxf(acc[m], fmaxf(h, 0.0f));
                    }
                }
            }
        }
        __syncwarp();
#pragma unroll
        for (int m = 0; m < 8; ++m) {
            acc[m] = fmaxf(acc[m], __shfl_xor_sync(0xffffffffu, acc[m], 1, 8));
            acc[m] = fmaxf(acc[m], __shfl_xor_sync(0xffffffffu, acc[m], 2, 8));
            acc[m] = fmaxf(acc[m], __shfl_xor_sync(0xffffffffu, acc[m], 4, 8));
        }
        cnt = min(s_cnt[p], CAPN);

        // epilogue: output o = r, then h0b channels 2r, 2r+1 via shfl
        float v = sB2a[r];
#pragma unroll
        for (int m = 0; m < 8; ++m) v = fmaf(acc[m], sW2a[m * 8 + r], v);
        v = celu1(v);

        float h0 = sB1b[2 * r], h1 = sB1b[2 * r + 1];
#pragma unroll
        for (int o = 0; o < 8; ++o) {
            const float vo = __shfl_sync(0xffffffffu, v, o, 8);
            h0 = fmaf(vo, sWbx[o * 16 + 2 * r + 0], h0);
            h1 = fmaf(vo, sWbx[o * 16 + 2 * r + 1], h1);
        }
        *(float2*)&g_h0b[(size_t)i * 16 + 2 * r] = make_float2(h0, h1);
    }
    grid_barrier();

    // ---- P3: layer b (channel-split: lane owns channels 2r, 2r+1) ----
    {
        if (gtid < NCELL) g_cell_cnt[gtid] = 0;   // reset for next graph replay

        float a0 = -INFINITY, a1 = -INFINITY;
        for (int n = 0; n < cnt; ++n) {
            const float4 rel = s_nrel[p * CAPN + n];
            const int j = s_nidx[p * CAPN + n];
            const float2 hb = *(const float2*)&g_h0b[(size_t)j * 16 + 2 * r];
            float h = hb.x;
            h = fmaf(rel.x, sWbr[0 * 16 + 2 * r], h);
            h = fmaf(rel.y, sWbr[1 * 16 + 2 * r], h);
            h = fmaf(rel.z, sWbr[2 * 16 + 2 * r], h);
            a0 = fmaxf(a0, fmaxf(h, 0.0f));
            h = hb.y;
            h = fmaf(rel.x, sWbr[0 * 16 + 2 * r + 1], h);
            h = fmaf(rel.y, sWbr[1 * 16 + 2 * r + 1], h);
            h = fmaf(rel.z, sWbr[2 * 16 + 2 * r + 1], h);
            a1 = fmaxf(a1, fmaxf(h, 0.0f));
        }
        __syncwarp();

        // v[2r], v[2r+1] = celu(accfull @ W2b + b2b), accfull gathered by shfl
        float v0 = sB2b[2 * r], v1 = sB2b[2 * r + 1];
#pragma unroll
        for (int mm = 0; mm < 8; ++mm) {
            const float am0 = __shfl_sync(0xffffffffu, a0, mm, 8);  // ch 2mm
            const float am1 = __shfl_sync(0xffffffffu, a1, mm, 8);  // ch 2mm+1
            v0 = fmaf(am0, sW2b[(2 * mm + 0) * 16 + 2 * r + 0], v0);
            v0 = fmaf(am1, sW2b[(2 * mm + 1) * 16 + 2 * r + 0], v0);
            v1 = fmaf(am0, sW2b[(2 * mm + 0) * 16 + 2 * r + 1], v1);
            v1 = fmaf(am1, sW2b[(2 * mm + 1) * 16 + 2 * r + 1], v1);
        }
        v0 = celu1(v0);
        v1 = celu1(v1);

        // h0c channels 4r..4r+3 = b1c + v @ W1c[0:16]
        float c0 = sB1c[4 * r + 0], c1 = sB1c[4 * r + 1];
        float c2 = sB1c[4 * r + 2], c3 = sB1c[4 * r + 3];
#pragma unroll
        for (int oo = 0; oo < 8; ++oo) {
            const float w0 = __shfl_sync(0xffffffffu, v0, oo, 8);   // out 2oo
            const float w1 = __shfl_sync(0xffffffffu, v1, oo, 8);   // out 2oo+1
            c0 = fmaf(w0, sWcx[(2 * oo) * 32 + 4 * r + 0], c0);
            c1 = fmaf(w0, sWcx[(2 * oo) * 32 + 4 * r + 1], c1);
            c2 = fmaf(w0, sWcx[(2 * oo) * 32 + 4 * r + 2], c2);
            c3 = fmaf(w0, sWcx[(2 * oo) * 32 + 4 * r + 3], c3);
            c0 = fmaf(w1, sWcx[(2 * oo + 1) * 32 + 4 * r + 0], c0);
            c1 = fmaf(w1, sWcx[(2 * oo + 1) * 32 + 4 * r + 1], c1);
            c2 = fmaf(w1, sWcx[(2 * oo + 1) * 32 + 4 * r + 2], c2);
            c3 = fmaf(w1, sWcx[(2 * oo + 1) * 32 + 4 * r + 3], c3);
        }
        *(float4*)&g_h0c[(size_t)i * 32 + 4 * r] = make_float4(c0, c1, c2, c3);
    }
    grid_barrier();

    // ---- P4: layer c (channel-split: lane owns channels 4r..4r+3) ----
    {
        float acc[4];
#pragma unroll
        for (int m = 0; m < 4; ++m) acc[m] = -INFINITY;

        for (int n = 0; n < cnt; ++n) {
            const float4 rel = s_nrel[p * CAPN + n];
            const int j = s_nidx[p * CAPN + n];
            const float4 hc = *(const float4*)&g_h0c[(size_t)j * 32 + 4 * r];
            const float hj[4] = {hc.x, hc.y, hc.z, hc.w};
#pragma unroll
            for (int m = 0; m < 4; ++m) {
                float h = hj[m];
                h = fmaf(rel.x, sWcr[0 * 32 + 4 * r + m], h);
                h = fmaf(rel.y, sWcr[1 * 32 + 4 * r + m], h);
                h = fmaf(rel.z, sWcr[2 * 32 + 4 * r + m], h);
                acc[m] = fmaxf(acc[m], fmaxf(h, 0.0f));
            }
        }
        __syncwarp();

        float s0 = sB2c[4 * r + 0], s1 = sB2c[4 * r + 1];
        float s2 = sB2c[4 * r + 2], s3 = sB2c[4 * r + 3];
#pragma unroll
        for (int mm = 0; mm < 8; ++mm) {
            float am[4];
#pragma unroll
            for (int k = 0; k < 4; ++k)
                am[k] = __shfl_sync(0xffffffffu, acc[k], mm, 8);    // ch 4mm+k
#pragma unroll
            for (int k = 0; k < 4; ++k) {
                const int row = 4 * mm + k;
                s0 = fmaf(am[k], sW2c[row * 32 + 4 * r + 0], s0);
                s1 = fmaf(am[k], sW2c[row * 32 + 4 * r + 1], s1);
                s2 = fmaf(am[k], sW2c[row * 32 + 4 * r + 2], s2);
                s3 = fmaf(am[k], sW2c[row * 32 + 4 * r + 3], s3);
            }
        }
        float4* dst = (float4*)(out + (size_t)NPTS * 3 + (size_t)i * 32 + 4 * r);
        *dst = make_float4(celu1(s0), celu1(s1), celu1(s2), celu1(s3));
    }
}

// ---------------------------------------------------------------------------
// Launch. Inputs: 0 pos | 1 rgb (unused) | 2 batch |
//  3 W1a[6,8] 4 b1a 5 W2a 6 b2a | 7 W1b[11,16] 8 b1b 9 W2b 10 b2b
// 11 W1c[19,32] 12 b1c 13 W2c 14 b2c
// Output: [pos(3N) | feat(32N) | batch(N)] float32.
// ---------------------------------------------------------------------------
extern "C" void kernel_launch(void* const* d_in, const int* in_sizes, int n_in,
                              void* d_out, int out_size)
{
    fused_kernel<<<NBLK, NTHR>>>(
        (const float*)d_in[0], (const int*)d_in[2],
        (const float*)d_in[3],  (const float*)d_in[4],
        (const float*)d_in[5],  (const float*)d_in[6],
        (const float*)d_in[7],  (const float*)d_in[8],
        (const float*)d_in[9],  (const float*)d_in[10],
        (const float*)d_in[11], (const float*)d_in[12],
        (const float*)d_in[13], (const float*)d_in[14],
        (float*)d_out);
}